// round 2
// baseline (speedup 1.0000x reference)
#include <cuda_runtime.h>
#include <cstdint>

#define N_IMG 8192

// ---------------- scratch (device globals; no allocations) ----------------
__device__ float    g_Ppart[128 * 1024];     // partial batch sums of x
__device__ float    g_thr[20];               // per-channel BN mean (threshold)
__device__ unsigned g_b1[N_IMG * 196];       // binarized pool1: 20 channel bits per (n,py,px)
__device__ unsigned g_wp2[50 * 25];          // conv2 sign(W)>0 masks (20 bits over c)
__device__ unsigned g_wz2[50 * 25];          // conv2 W==0 masks
__device__ int      g_zflag2;                // any zero conv2 weight
__device__ unsigned g_wpl[500 * 40];         // linear sign(W)>0 masks (1250 bits)
__device__ unsigned g_wzl[500 * 40];         // linear W==0 masks
__device__ int      g_zflagl;
__device__ float    g_alphal[500];           // linear alpha = mean(|W|, dim=1)
__device__ unsigned g_Bp[N_IMG * 40];        // sign(+1) bit-plane into linear
__device__ unsigned g_Bn[N_IMG * 40];        // sign(-1) bit-plane into linear

// ---------------- K1: batch-sum of x per pixel (deterministic tree) -------
__global__ __launch_bounds__(256) void k_colsum(const float* __restrict__ x) {
    int b = blockIdx.x;            // 0..127, 64 images each
    int t = threadIdx.x;           // 0..255, 4 pixels each
    const float* base = x + (size_t)b * 64 * 1024 + t * 4;
    float4 acc = make_float4(0.f, 0.f, 0.f, 0.f);
    for (int i = 0; i < 64; ++i) {
        float4 v = *(const float4*)(base + (size_t)i * 1024);
        acc.x += v.x; acc.y += v.y; acc.z += v.z; acc.w += v.w;
    }
    *(float4*)(g_Ppart + b * 1024 + t * 4) = acc;
}

// ---------------- K1b: reduce partials -> P, T[5][5], thresholds ----------
__global__ __launch_bounds__(1024) void k_thr(const float* __restrict__ w1) {
    __shared__ double Ps[1024];
    __shared__ double Ts[25];
    int t = threadIdx.x;
    double s = 0.0;
    for (int i = 0; i < 128; ++i) s += (double)g_Ppart[i * 1024 + t];
    Ps[t] = s;
    __syncthreads();
    if (t < 25) {
        int dy = t / 5, dx = t % 5;
        double a = 0.0;
        for (int i = 0; i < 28; ++i)
            for (int j = 0; j < 28; ++j)
                a += Ps[(i + dy) * 32 + (j + dx)];
        Ts[t] = a;
    }
    __syncthreads();
    if (t < 20) {
        double d = 0.0;
        for (int k = 0; k < 25; ++k) d += (double)w1[t * 25 + k] * Ts[k];
        g_thr[t] = (float)(d / (8192.0 * 28.0 * 28.0));
    }
}

// ---------------- Kprep: weight bitmasks + alpha_l ------------------------
__global__ void k_prep(const float* __restrict__ w2, const float* __restrict__ wl) {
    int gid = blockIdx.x * blockDim.x + threadIdx.x;
    int nth = gridDim.x * blockDim.x;
    // conv2 masks: (oc, dy, dx) word over 20 channels
    for (int e = gid; e < 1250; e += nth) {
        int oc = e / 25, d = e % 25;
        unsigned mp = 0, mz = 0;
        for (int c = 0; c < 20; ++c) {
            float w = w2[oc * 500 + c * 25 + d];
            if (w > 0.f) mp |= 1u << c;
            else if (w == 0.f) mz |= 1u << c;
        }
        g_wp2[e] = mp; g_wz2[e] = mz;
        if (mz) atomicOr(&g_zflag2, 1);
    }
    // linear masks: 500 rows x 40 words (1250 bits + zero padding)
    for (int e = gid; e < 500 * 40; e += nth) {
        int j = e / 40, wi = e % 40;
        unsigned mp = 0, mz = 0;
        for (int b = 0; b < 32; ++b) {
            int i = wi * 32 + b;
            if (i < 1250) {
                float w = wl[j * 1250 + i];
                if (w > 0.f) mp |= 1u << b;
                else if (w == 0.f) mz |= 1u << b;
            }
        }
        g_wpl[e] = mp; g_wzl[e] = mz;
        if (mz) atomicOr(&g_zflagl, 1);
    }
    // alpha_l in fp64
    for (int j = gid; j < 500; j += nth) {
        double s = 0.0;
        for (int i = 0; i < 1250; ++i) s += fabs((double)wl[j * 1250 + i]);
        g_alphal[j] = (float)(s / 1250.0);
    }
}

// ---------------- K2: conv1 + threshold + 2x2 pool + channel bit-pack -----
__global__ __launch_bounds__(224) void k_conv1(const float* __restrict__ x,
                                               const float* __restrict__ w1) {
    __shared__ float xs[1024];
    __shared__ float ws[20 * 28];
    __shared__ float thr_s[20];
    int n = blockIdx.x, t = threadIdx.x;
    for (int i = t; i < 1024; i += 224) xs[i] = x[(size_t)n * 1024 + i];
    for (int i = t; i < 500; i += 224) ws[(i / 25) * 28 + (i % 25)] = w1[i];
    if (t < 20) thr_s[t] = g_thr[t];
    __syncthreads();
    if (t < 196) {
        int py = t / 14, px = t % 14;
        float xp[6][6];
        const float* xb = &xs[(py * 2) * 32 + px * 2];
#pragma unroll
        for (int r = 0; r < 6; ++r) {
#pragma unroll
            for (int c2 = 0; c2 < 3; ++c2) {
                float2 v = *(const float2*)(xb + r * 32 + c2 * 2);
                xp[r][c2 * 2] = v.x; xp[r][c2 * 2 + 1] = v.y;
            }
        }
        unsigned word = 0;
#pragma unroll 1
        for (int c = 0; c < 20; ++c) {
            const float* wc = &ws[c * 28];
            float a0 = 0.f, a1 = 0.f, a2 = 0.f, a3 = 0.f;
#pragma unroll
            for (int dy = 0; dy < 5; ++dy) {
#pragma unroll
                for (int dx = 0; dx < 5; ++dx) {
                    float w = wc[dy * 5 + dx];
                    a0 = fmaf(w, xp[dy][dx],         a0);
                    a1 = fmaf(w, xp[dy][dx + 1],     a1);
                    a2 = fmaf(w, xp[dy + 1][dx],     a2);
                    a3 = fmaf(w, xp[dy + 1][dx + 1], a3);
                }
            }
            float m = fmaxf(fmaxf(a0, a1), fmaxf(a2, a3));
            if (m > thr_s[c]) word |= (1u << c);
        }
        g_b1[n * 196 + t] = word;
    }
}

// ---------------- K3: XNOR conv2 + sign(maxpool) -> bit-planes ------------
__global__ __launch_bounds__(320) void k_conv2() {
    __shared__ unsigned Bs[196];
    __shared__ int pc[196];
    __shared__ int PB[100];
    __shared__ unsigned Wps[50 * 25];
    __shared__ unsigned Wzs[50 * 25];
    int n = blockIdx.x, t = threadIdx.x;
    for (int i = t; i < 196; i += 320) { unsigned b = g_b1[n * 196 + i]; Bs[i] = b; pc[i] = __popc(b); }
    for (int i = t; i < 1250; i += 320) { Wps[i] = g_wp2[i]; Wzs[i] = g_wz2[i]; }
    __syncthreads();
    if (t < 100) {
        int y = t / 10, xx = t % 10;
        int s = 0;
#pragma unroll
        for (int dy = 0; dy < 5; ++dy)
#pragma unroll
            for (int dx = 0; dx < 5; ++dx) s += pc[(y + dy) * 14 + xx + dx];
        PB[t] = s;
    }
    __syncthreads();
    int zf = g_zflag2;
    int lane = t & 31, w = t >> 5;
#pragma unroll 1
    for (int k = 0; k < 4; ++k) {
        int f = k * 320 + t;
        int bitP = 0, bitN = 0;
        if (f < 1250) {
            int oc = f / 25, rem = f - oc * 25;
            int r = rem / 5, cx = rem - r * 5;
            unsigned bp[6][6];
#pragma unroll
            for (int rr = 0; rr < 6; ++rr)
#pragma unroll
                for (int cc = 0; cc < 6; ++cc)
                    bp[rr][cc] = Bs[(2 * r + rr) * 14 + 2 * cx + cc];
            const unsigned* W = &Wps[oc * 25];
            int best = -1000000;
#pragma unroll
            for (int oy = 0; oy < 2; ++oy) {
#pragma unroll
                for (int ox = 0; ox < 2; ++ox) {
                    int acc = 0;
#pragma unroll
                    for (int dy = 0; dy < 5; ++dy)
#pragma unroll
                        for (int dx = 0; dx < 5; ++dx)
                            acc += __popc(bp[oy + dy][ox + dx] & W[dy * 5 + dx]);
                    int v = 2 * acc - PB[(2 * r + oy) * 10 + 2 * cx + ox];
                    if (zf) {  // uniform, never taken with this dataset
                        const unsigned* Wz = &Wzs[oc * 25];
                        int az = 0;
                        for (int dy = 0; dy < 5; ++dy)
                            for (int dx = 0; dx < 5; ++dx)
                                az += __popc(bp[oy + dy][ox + dx] & Wz[dy * 5 + dx]);
                        v += az;
                    }
                    best = max(best, v);
                }
            }
            bitP = best > 0; bitN = best < 0;
        }
        unsigned mp = __ballot_sync(0xffffffffu, bitP);
        unsigned mn = __ballot_sync(0xffffffffu, bitN);
        if (lane == 0) {
            int wi = k * 10 + w;
            g_Bp[n * 40 + wi] = mp;
            g_Bn[n * 40 + wi] = mn;
        }
    }
}

// ---------------- K4: binary linear + clip + fc (8 images / block) --------
__global__ __launch_bounds__(256) void k_dense(const float* __restrict__ fcw,
                                               const float* __restrict__ fcb,
                                               float* __restrict__ out) {
    extern __shared__ unsigned sm[];
    unsigned* Ws  = sm;                       // 500*41 (padded, conflict-free)
    unsigned* Bps = Ws + 500 * 41;            // 8*40
    unsigned* Bns = Bps + 8 * 40;             // 8*40
    int*      pcP = (int*)(Bns + 8 * 40);     // 8
    int*      pcN = pcP + 8;                  // 8
    float*    hs  = (float*)(pcN + 8);        // 8*500
    int t = threadIdx.x;
    int n0 = blockIdx.x * 8;
    for (int i = t; i < 500 * 40; i += 256) Ws[(i / 40) * 41 + (i % 40)] = g_wpl[i];
    for (int i = t; i < 320; i += 256) {
        int img = i / 40, wi = i % 40;
        Bps[img * 40 + wi] = g_Bp[(size_t)(n0 + img) * 40 + wi];
        Bns[img * 40 + wi] = g_Bn[(size_t)(n0 + img) * 40 + wi];
    }
    __syncthreads();
    if (t < 16) {
        int img = t >> 1;
        const unsigned* src = (t & 1) ? &Bns[img * 40] : &Bps[img * 40];
        int s = 0;
        for (int k = 0; k < 40; ++k) s += __popc(src[k]);
        if (t & 1) pcN[img] = s; else pcP[img] = s;
    }
    __syncthreads();
    int zf = g_zflagl;
    for (int j = t; j < 500; j += 256) {
        unsigned wr[40];
#pragma unroll
        for (int k = 0; k < 40; ++k) wr[k] = Ws[j * 41 + k];
        float al = g_alphal[j];
#pragma unroll 1
        for (int img = 0; img < 8; ++img) {
            int ap = 0, an = 0;
#pragma unroll
            for (int k = 0; k < 40; ++k) {
                ap += __popc(Bps[img * 40 + k] & wr[k]);
                an += __popc(Bns[img * 40 + k] & wr[k]);
            }
            int vi = 2 * (ap - an) - pcP[img] + pcN[img];
            if (zf) {  // uniform, never taken with this dataset
                int cp = 0, cn = 0;
                for (int k = 0; k < 40; ++k) {
                    unsigned z = g_wzl[j * 40 + k];
                    cp += __popc(Bps[img * 40 + k] & z);
                    cn += __popc(Bns[img * 40 + k] & z);
                }
                vi += cp - cn;
            }
            float h = fminf(fmaxf((float)vi * al, -1.f), 1.f);
            hs[img * 500 + j] = h;
        }
    }
    __syncthreads();
    int w = t >> 5, lane = t & 31;   // warp w -> image w
    for (int lg = 0; lg < 10; ++lg) {
        float p = 0.f;
        for (int j = lane; j < 500; j += 32)
            p += hs[w * 500 + j] * __ldg(&fcw[lg * 500 + j]);
#pragma unroll
        for (int o = 16; o; o >>= 1) p += __shfl_down_sync(0xffffffffu, p, o);
        if (lane == 0) out[(size_t)(n0 + w) * 10 + lg] = p + fcb[lg];
    }
}

// ---------------- launch ---------------------------------------------------
extern "C" void kernel_launch(void* const* d_in, const int* in_sizes, int n_in,
                              void* d_out, int out_size) {
    const float* x   = (const float*)d_in[0];
    const float* w1  = (const float*)d_in[1];
    const float* w2  = (const float*)d_in[2];
    const float* wl  = (const float*)d_in[3];
    const float* fcw = (const float*)d_in[4];
    const float* fcb = (const float*)d_in[5];
    float* out = (float*)d_out;

    size_t dense_smem = (500 * 41 + 8 * 40 * 2 + 16) * 4 + 8 * 500 * 4;
    cudaFuncSetAttribute(k_dense, cudaFuncAttributeMaxDynamicSharedMemorySize,
                         (int)dense_smem);

    k_colsum<<<128, 256>>>(x);
    k_thr<<<1, 1024>>>(w1);
    k_prep<<<96, 256>>>(w2, wl);
    k_conv1<<<8192, 224>>>(x, w1);
    k_conv2<<<8192, 320>>>();
    k_dense<<<1024, 256, dense_smem>>>(fcw, fcb, out);
}

// round 3
// speedup vs baseline: 1.0212x; 1.0212x over previous
#include <cuda_runtime.h>
#include <cstdint>

#define N_IMG 8192

// ---------------- scratch (device globals; no allocations) ----------------
__device__ float    g_Ppart[128 * 1024];     // partial batch sums of x
__device__ float    g_thr[20];               // per-channel BN mean (threshold)
__device__ unsigned g_b1[N_IMG * 196];       // binarized pool1: 20 channel bits per (n,py,px)
__device__ unsigned g_wp2[50 * 25];          // conv2 sign(W)>0 masks (20 bits over c)
__device__ unsigned g_wz2[50 * 25];          // conv2 W==0 masks
__device__ int      g_zflag2;                // any zero conv2 weight
__device__ unsigned g_wpl[500 * 40];         // linear sign(W)>0 masks (1250 bits)
__device__ unsigned g_wzl[500 * 40];         // linear W==0 masks
__device__ int      g_zflagl;
__device__ float    g_alphal[500];           // linear alpha = mean(|W|, dim=1)
__device__ unsigned g_Bp[N_IMG * 40];        // sign(+1) bit-plane into linear
__device__ unsigned g_Bn[N_IMG * 40];        // sign(-1) bit-plane into linear

// ---------------- packed f32x2 helpers ------------------------------------
__device__ __forceinline__ unsigned long long ffma2(unsigned long long a,
                                                    unsigned long long b,
                                                    unsigned long long c) {
    unsigned long long d;
    asm("fma.rn.f32x2 %0, %1, %2, %3;" : "=l"(d) : "l"(a), "l"(b), "l"(c));
    return d;
}
__device__ __forceinline__ unsigned long long packf2(float lo, float hi) {
    unsigned long long v;
    asm("mov.b64 %0, {%1, %2};" : "=l"(v) : "f"(lo), "f"(hi));
    return v;
}
__device__ __forceinline__ void unpackf2(unsigned long long v, float& lo, float& hi) {
    asm("mov.b64 {%0, %1}, %2;" : "=f"(lo), "=f"(hi) : "l"(v));
}

// ---------------- K1: batch-sum of x per pixel (deterministic tree) -------
__global__ __launch_bounds__(256) void k_colsum(const float* __restrict__ x) {
    int b = blockIdx.x;            // 0..127, 64 images each
    int t = threadIdx.x;           // 0..255, 4 pixels each
    const float* base = x + (size_t)b * 64 * 1024 + t * 4;
    float4 acc = make_float4(0.f, 0.f, 0.f, 0.f);
    for (int i = 0; i < 64; ++i) {
        float4 v = *(const float4*)(base + (size_t)i * 1024);
        acc.x += v.x; acc.y += v.y; acc.z += v.z; acc.w += v.w;
    }
    *(float4*)(g_Ppart + b * 1024 + t * 4) = acc;
}

// ---------------- K1b: reduce partials -> P, T[5][5], thresholds ----------
__global__ __launch_bounds__(1024) void k_thr(const float* __restrict__ w1) {
    __shared__ double Ps[1024];
    __shared__ double Ts[25];
    int t = threadIdx.x;
    double s = 0.0;
    for (int i = 0; i < 128; ++i) s += (double)g_Ppart[i * 1024 + t];
    Ps[t] = s;
    __syncthreads();
    if (t < 25) {
        int dy = t / 5, dx = t % 5;
        double a = 0.0;
        for (int i = 0; i < 28; ++i)
            for (int j = 0; j < 28; ++j)
                a += Ps[(i + dy) * 32 + (j + dx)];
        Ts[t] = a;
    }
    __syncthreads();
    if (t < 20) {
        double d = 0.0;
        for (int k = 0; k < 25; ++k) d += (double)w1[t * 25 + k] * Ts[k];
        g_thr[t] = (float)(d / (8192.0 * 28.0 * 28.0));
    }
}

// ---------------- Kprep: weight bitmasks + alpha_l ------------------------
__global__ void k_prep(const float* __restrict__ w2, const float* __restrict__ wl) {
    int gid = blockIdx.x * blockDim.x + threadIdx.x;
    int nth = gridDim.x * blockDim.x;
    // conv2 masks: (oc, dy, dx) word over 20 channels
    for (int e = gid; e < 1250; e += nth) {
        int oc = e / 25, d = e % 25;
        unsigned mp = 0, mz = 0;
        for (int c = 0; c < 20; ++c) {
            float w = w2[oc * 500 + c * 25 + d];
            if (w > 0.f) mp |= 1u << c;
            else if (w == 0.f) mz |= 1u << c;
        }
        g_wp2[e] = mp; g_wz2[e] = mz;
        if (mz) atomicOr(&g_zflag2, 1);
    }
    // linear masks: 500 rows x 40 words (1250 bits + zero padding)
    for (int e = gid; e < 500 * 40; e += nth) {
        int j = e / 40, wi = e % 40;
        unsigned mp = 0, mz = 0;
        for (int b = 0; b < 32; ++b) {
            int i = wi * 32 + b;
            if (i < 1250) {
                float w = wl[j * 1250 + i];
                if (w > 0.f) mp |= 1u << b;
                else if (w == 0.f) mz |= 1u << b;
            }
        }
        g_wpl[e] = mp; g_wzl[e] = mz;
        if (mz) atomicOr(&g_zflagl, 1);
    }
    // alpha_l in fp64
    for (int j = gid; j < 500; j += nth) {
        double s = 0.0;
        for (int i = 0; i < 1250; ++i) s += fabs((double)wl[j * 1250 + i]);
        g_alphal[j] = (float)(s / 1250.0);
    }
}

// ---------------- K2: conv1 (FFMA2) + threshold + 2x2 pool + bit-pack -----
__global__ __launch_bounds__(224) void k_conv1(const float* __restrict__ x,
                                               const float* __restrict__ w1) {
    __shared__ float xs[1024];
    __shared__ unsigned long long ws2[500];   // duplicated weight pairs (w,w)
    __shared__ float thr_s[20];
    int n = blockIdx.x, t = threadIdx.x;
    for (int i = t; i < 1024; i += 224) xs[i] = x[(size_t)n * 1024 + i];
    for (int i = t; i < 500; i += 224) {
        float w = w1[i];
        ws2[i] = packf2(w, w);
    }
    if (t < 20) thr_s[t] = g_thr[t];
    __syncthreads();
    if (t < 196) {
        int py = t / 14, px = t % 14;
        const float* xb = &xs[(py * 2) * 32 + px * 2];
        // sliding x pairs: xp[r][dx] = (x[r][dx], x[r][dx+1]), dx=0..4
        unsigned long long xp[6][5];
#pragma unroll
        for (int r = 0; r < 6; ++r) {
            float2 v0 = *(const float2*)(xb + r * 32);
            float2 v1 = *(const float2*)(xb + r * 32 + 2);
            float2 v2 = *(const float2*)(xb + r * 32 + 4);
            xp[r][0] = packf2(v0.x, v0.y);
            xp[r][1] = packf2(v0.y, v1.x);
            xp[r][2] = packf2(v1.x, v1.y);
            xp[r][3] = packf2(v1.y, v2.x);
            xp[r][4] = packf2(v2.x, v2.y);
        }
        unsigned word = 0;
#pragma unroll 1
        for (int c = 0; c < 20; ++c) {
            const unsigned long long* wc = &ws2[c * 25];
            unsigned long long a01 = 0ull, a23 = 0ull;  // (a0,a1), (a2,a3)
#pragma unroll
            for (int dy = 0; dy < 5; ++dy) {
#pragma unroll
                for (int dx = 0; dx < 5; ++dx) {
                    unsigned long long w = wc[dy * 5 + dx];
                    a01 = ffma2(w, xp[dy][dx], a01);
                    a23 = ffma2(w, xp[dy + 1][dx], a23);
                }
            }
            float a0, a1, a2, a3;
            unpackf2(a01, a0, a1);
            unpackf2(a23, a2, a3);
            float m = fmaxf(fmaxf(a0, a1), fmaxf(a2, a3));
            if (m > thr_s[c]) word |= (1u << c);
        }
        g_b1[n * 196 + t] = word;
    }
}

// ---------------- K3: XNOR conv2 + sign(maxpool) -> bit-planes ------------
__global__ __launch_bounds__(320) void k_conv2() {
    __shared__ unsigned Bs[196];
    __shared__ int pc[196];
    __shared__ int PB[100];
    __shared__ unsigned Wps[50 * 25];
    __shared__ unsigned Wzs[50 * 25];
    int n = blockIdx.x, t = threadIdx.x;
    for (int i = t; i < 196; i += 320) { unsigned b = g_b1[n * 196 + i]; Bs[i] = b; pc[i] = __popc(b); }
    for (int i = t; i < 1250; i += 320) { Wps[i] = g_wp2[i]; Wzs[i] = g_wz2[i]; }
    __syncthreads();
    if (t < 100) {
        int y = t / 10, xx = t % 10;
        int s = 0;
#pragma unroll
        for (int dy = 0; dy < 5; ++dy)
#pragma unroll
            for (int dx = 0; dx < 5; ++dx) s += pc[(y + dy) * 14 + xx + dx];
        PB[t] = s;
    }
    __syncthreads();
    int zf = g_zflag2;
    int lane = t & 31, w = t >> 5;
#pragma unroll 1
    for (int k = 0; k < 4; ++k) {
        int f = k * 320 + t;
        int bitP = 0, bitN = 0;
        if (f < 1250) {
            int oc = f / 25, rem = f - oc * 25;
            int r = rem / 5, cx = rem - r * 5;
            unsigned bp[6][6];
#pragma unroll
            for (int rr = 0; rr < 6; ++rr)
#pragma unroll
                for (int cc = 0; cc < 6; ++cc)
                    bp[rr][cc] = Bs[(2 * r + rr) * 14 + 2 * cx + cc];
            const unsigned* W = &Wps[oc * 25];
            int best = -1000000;
#pragma unroll
            for (int oy = 0; oy < 2; ++oy) {
#pragma unroll
                for (int ox = 0; ox < 2; ++ox) {
                    int acc = 0;
#pragma unroll
                    for (int dy = 0; dy < 5; ++dy)
#pragma unroll
                        for (int dx = 0; dx < 5; ++dx)
                            acc += __popc(bp[oy + dy][ox + dx] & W[dy * 5 + dx]);
                    int v = 2 * acc - PB[(2 * r + oy) * 10 + 2 * cx + ox];
                    if (zf) {  // uniform, never taken with this dataset
                        const unsigned* Wz = &Wzs[oc * 25];
                        int az = 0;
                        for (int dy = 0; dy < 5; ++dy)
                            for (int dx = 0; dx < 5; ++dx)
                                az += __popc(bp[oy + dy][ox + dx] & Wz[dy * 5 + dx]);
                        v += az;
                    }
                    best = max(best, v);
                }
            }
            bitP = best > 0; bitN = best < 0;
        }
        unsigned mp = __ballot_sync(0xffffffffu, bitP);
        unsigned mn = __ballot_sync(0xffffffffu, bitN);
        if (lane == 0) {
            int wi = k * 10 + w;
            g_Bp[n * 40 + wi] = mp;
            g_Bn[n * 40 + wi] = mn;
        }
    }
}

// ---------------- K4: binary linear (XNOR-LOP3) + clip + fc ---------------
__global__ __launch_bounds__(256) void k_dense(const float* __restrict__ fcw,
                                               const float* __restrict__ fcb,
                                               float* __restrict__ out) {
    extern __shared__ unsigned sm[];
    unsigned* Ws  = sm;                       // 500*41 (padded, conflict-free)
    unsigned* Bps = Ws + 500 * 41;            // 8*40  sign bit-plane (+1)
    unsigned* Bns = Bps + 8 * 40;             // 8*40  sign bit-plane (-1), zf path only
    unsigned* Us  = Bns + 8 * 40;             // 8*40  nonzero mask = Bp|Bn
    int*      pcU = (int*)(Us + 8 * 40);      // 8
    float*    hs  = (float*)(pcU + 8);        // 8*500
    int t = threadIdx.x;
    int n0 = blockIdx.x * 8;
    for (int i = t; i < 500 * 40; i += 256) Ws[(i / 40) * 41 + (i % 40)] = g_wpl[i];
    for (int i = t; i < 320; i += 256) {
        int img = i / 40, wi = i % 40;
        unsigned bp = g_Bp[(size_t)(n0 + img) * 40 + wi];
        unsigned bn = g_Bn[(size_t)(n0 + img) * 40 + wi];
        Bps[img * 40 + wi] = bp;
        Bns[img * 40 + wi] = bn;
        Us[img * 40 + wi]  = bp | bn;
    }
    __syncthreads();
    if (t < 8) {
        int s = 0;
        for (int k = 0; k < 40; ++k) s += __popc(Us[t * 40 + k]);
        pcU[t] = s;
    }
    __syncthreads();
    int zf = g_zflagl;
    for (int j = t; j < 500; j += 256) {
        unsigned wr[40];
#pragma unroll
        for (int k = 0; k < 40; ++k) wr[k] = Ws[j * 41 + k];
        float al = g_alphal[j];
#pragma unroll 1
        for (int img = 0; img < 8; ++img) {
            int m = 0;
#pragma unroll
            for (int k = 0; k < 40; ++k) {
                // agreement over nonzero lanes: one LOP3 per word
                m += __popc((~(Bps[img * 40 + k] ^ wr[k])) & Us[img * 40 + k]);
            }
            int vi = 2 * m - pcU[img];
            if (zf) {  // uniform, never taken with this dataset
                // w==0 positions were treated as w=-1 above (Wp bit 0); undo: += s
                int cp = 0, cn = 0;
                for (int k = 0; k < 40; ++k) {
                    unsigned z = g_wzl[j * 40 + k];
                    cp += __popc(Bps[img * 40 + k] & z);
                    cn += __popc(Bns[img * 40 + k] & z);
                }
                vi += cp - cn;
            }
            float h = fminf(fmaxf((float)vi * al, -1.f), 1.f);
            hs[img * 500 + j] = h;
        }
    }
    __syncthreads();
    int w = t >> 5, lane = t & 31;   // warp w -> image w
    for (int lg = 0; lg < 10; ++lg) {
        float p = 0.f;
        for (int j = lane; j < 500; j += 32)
            p += hs[w * 500 + j] * __ldg(&fcw[lg * 500 + j]);
#pragma unroll
        for (int o = 16; o; o >>= 1) p += __shfl_down_sync(0xffffffffu, p, o);
        if (lane == 0) out[(size_t)(n0 + w) * 10 + lg] = p + fcb[lg];
    }
}

// ---------------- launch ---------------------------------------------------
extern "C" void kernel_launch(void* const* d_in, const int* in_sizes, int n_in,
                              void* d_out, int out_size) {
    const float* x   = (const float*)d_in[0];
    const float* w1  = (const float*)d_in[1];
    const float* w2  = (const float*)d_in[2];
    const float* wl  = (const float*)d_in[3];
    const float* fcw = (const float*)d_in[4];
    const float* fcb = (const float*)d_in[5];
    float* out = (float*)d_out;

    size_t dense_smem = (500 * 41 + 8 * 40 * 3 + 8) * 4 + 8 * 500 * 4;
    cudaFuncSetAttribute(k_dense, cudaFuncAttributeMaxDynamicSharedMemorySize,
                         (int)dense_smem);

    k_colsum<<<128, 256>>>(x);
    k_thr<<<1, 1024>>>(w1);
    k_prep<<<96, 256>>>(w2, wl);
    k_conv1<<<8192, 224>>>(x, w1);
    k_conv2<<<8192, 320>>>();
    k_dense<<<1024, 256, dense_smem>>>(fcw, fcb, out);
}

// round 4
// speedup vs baseline: 1.4210x; 1.3915x over previous
#include <cuda_runtime.h>
#include <cstdint>

#define N_IMG 8192

// ---------------- scratch (device globals; no allocations) ----------------
__device__ float    g_Ppart[128 * 1024];     // partial batch sums of x
__device__ float    g_thr[20];               // per-channel BN mean (threshold)
__device__ unsigned g_b1[N_IMG * 196];       // binarized pool1: 20 channel bits per (n,py,px)
__device__ unsigned g_wp2[50 * 25];          // conv2 sign(W)>0 masks (20 bits over c)
__device__ unsigned g_wz2[50 * 25];          // conv2 W==0 masks
__device__ int      g_zflag2;                // any zero conv2 weight
__device__ unsigned g_wpl[500 * 40];         // linear sign(W)>0 masks (1250 bits)
__device__ unsigned g_wzl[500 * 40];         // linear W==0 masks
__device__ int      g_zflagl;
__device__ float    g_alphal[500];           // linear alpha = mean(|W|, dim=1)
__device__ unsigned g_Bp[N_IMG * 40];        // sign(+1) bit-plane into linear
__device__ unsigned g_Bn[N_IMG * 40];        // sign(-1) bit-plane into linear

// ---------------- K_pre: fused colsum + weight masks + alpha_l ------------
// blocks [0,128)   : batch-sum of x (64 images x 1024 pixels each)
// blocks [128,144) : conv2 + linear sign/zero bitmasks
// blocks [144,207) : alpha_l, one warp per output row (fixed shfl tree)
__global__ __launch_bounds__(256) void k_pre(const float* __restrict__ x,
                                             const float* __restrict__ w2,
                                             const float* __restrict__ wl) {
    int b = blockIdx.x, t = threadIdx.x;
    if (b < 128) {
        const float* base = x + (size_t)b * 64 * 1024 + t * 4;
        float4 acc = make_float4(0.f, 0.f, 0.f, 0.f);
        for (int i = 0; i < 64; ++i) {
            float4 v = *(const float4*)(base + (size_t)i * 1024);
            acc.x += v.x; acc.y += v.y; acc.z += v.z; acc.w += v.w;
        }
        *(float4*)(g_Ppart + b * 1024 + t * 4) = acc;
    } else if (b < 144) {
        int gid = (b - 128) * 256 + t;           // 0..4095
        if (gid < 1250) {                         // conv2 masks
            int oc = gid / 25, d = gid % 25;
            unsigned mp = 0, mz = 0;
            for (int c = 0; c < 20; ++c) {
                float w = w2[oc * 500 + c * 25 + d];
                if (w > 0.f) mp |= 1u << c;
                else if (w == 0.f) mz |= 1u << c;
            }
            g_wp2[gid] = mp; g_wz2[gid] = mz;
            if (mz) atomicOr(&g_zflag2, 1);
        }
        for (int e = gid; e < 500 * 40; e += 4096) {  // linear masks
            int j = e / 40, wi = e % 40;
            unsigned mp = 0, mz = 0;
            for (int bit = 0; bit < 32; ++bit) {
                int i = wi * 32 + bit;
                if (i < 1250) {
                    float w = wl[j * 1250 + i];
                    if (w > 0.f) mp |= 1u << bit;
                    else if (w == 0.f) mz |= 1u << bit;
                }
            }
            g_wpl[e] = mp; g_wzl[e] = mz;
            if (mz) atomicOr(&g_zflagl, 1);
        }
    } else {
        int w = (b - 144) * 8 + (t >> 5);        // row index
        int lane = t & 31;
        if (w < 500) {
            double s = 0.0;
            for (int i = lane; i < 1250; i += 32)
                s += fabs((double)wl[w * 1250 + i]);
#pragma unroll
            for (int o = 16; o; o >>= 1) s += __shfl_down_sync(0xffffffffu, s, o);
            if (lane == 0) g_alphal[w] = (float)(s / 1250.0);
        }
    }
}

// ---------------- K1b: reduce partials -> P, T[5][5], thresholds ----------
__global__ __launch_bounds__(1024) void k_thr(const float* __restrict__ w1) {
    __shared__ double Ps[1024];
    __shared__ double Ts[25];
    int t = threadIdx.x;
    double s0 = 0.0, s1 = 0.0;
    for (int i = 0; i < 128; i += 2) {
        s0 += (double)g_Ppart[i * 1024 + t];
        s1 += (double)g_Ppart[(i + 1) * 1024 + t];
    }
    Ps[t] = s0 + s1;
    __syncthreads();
    if (t < 800) {                    // 25 taps x 32 lanes, fixed shfl tree
        int g = t >> 5, lane = t & 31;
        int dy = g / 5, dx = g % 5;
        double a = 0.0;
        for (int idx = lane; idx < 784; idx += 32) {
            int i = idx / 28, j = idx % 28;
            a += Ps[(i + dy) * 32 + (j + dx)];
        }
#pragma unroll
        for (int o = 16; o; o >>= 1) a += __shfl_down_sync(0xffffffffu, a, o);
        if (lane == 0) Ts[g] = a;
    }
    __syncthreads();
    if (t < 20) {
        double d = 0.0;
        for (int k = 0; k < 25; ++k) d += (double)w1[t * 25 + k] * Ts[k];
        g_thr[t] = (float)(d / (8192.0 * 28.0 * 28.0));
    }
}

// ---------------- K2: conv1 + threshold + 2x2 pool + channel bit-pack -----
__global__ __launch_bounds__(224) void k_conv1(const float* __restrict__ x,
                                               const float* __restrict__ w1) {
    __shared__ float xs[1024];
    __shared__ float ws[20 * 28];
    __shared__ float thr_s[20];
    int n = blockIdx.x, t = threadIdx.x;
    for (int i = t; i < 1024; i += 224) xs[i] = x[(size_t)n * 1024 + i];
    for (int i = t; i < 500; i += 224) ws[(i / 25) * 28 + (i % 25)] = w1[i];
    if (t < 20) thr_s[t] = g_thr[t];
    __syncthreads();
    if (t < 196) {
        int py = t / 14, px = t % 14;
        float xp[6][6];
        const float* xb = &xs[(py * 2) * 32 + px * 2];
#pragma unroll
        for (int r = 0; r < 6; ++r) {
#pragma unroll
            for (int c2 = 0; c2 < 3; ++c2) {
                float2 v = *(const float2*)(xb + r * 32 + c2 * 2);
                xp[r][c2 * 2] = v.x; xp[r][c2 * 2 + 1] = v.y;
            }
        }
        unsigned word = 0;
#pragma unroll 1
        for (int c = 0; c < 20; ++c) {
            const float* wc = &ws[c * 28];
            float a0 = 0.f, a1 = 0.f, a2 = 0.f, a3 = 0.f;
#pragma unroll
            for (int dy = 0; dy < 5; ++dy) {
#pragma unroll
                for (int dx = 0; dx < 5; ++dx) {
                    float w = wc[dy * 5 + dx];
                    a0 = fmaf(w, xp[dy][dx],         a0);
                    a1 = fmaf(w, xp[dy][dx + 1],     a1);
                    a2 = fmaf(w, xp[dy + 1][dx],     a2);
                    a3 = fmaf(w, xp[dy + 1][dx + 1], a3);
                }
            }
            float m = fmaxf(fmaxf(a0, a1), fmaxf(a2, a3));
            if (m > thr_s[c]) word |= (1u << c);
        }
        g_b1[n * 196 + t] = word;
    }
}

// ---------------- K3: XNOR conv2 + sign(maxpool), 4 images / block --------
#define C2_IMGS 4
__global__ __launch_bounds__(320) void k_conv2() {
    __shared__ unsigned Bs[C2_IMGS][196];
    __shared__ int pc[C2_IMGS][196];
    __shared__ int PB[C2_IMGS][100];
    __shared__ unsigned Wps[50 * 25];
    __shared__ unsigned Wzs[50 * 25];
    int n0 = blockIdx.x * C2_IMGS, t = threadIdx.x;
    for (int i = t; i < C2_IMGS * 196; i += 320) {
        int img = i / 196, p = i % 196;
        unsigned bv = g_b1[(size_t)(n0 + img) * 196 + p];
        Bs[img][p] = bv; pc[img][p] = __popc(bv);
    }
    int zf = g_zflag2;
    for (int i = t; i < 1250; i += 320) Wps[i] = g_wp2[i];
    if (zf) for (int i = t; i < 1250; i += 320) Wzs[i] = g_wz2[i];
    __syncthreads();
    if (t < 100) {
        int y = t / 10, xx = t % 10;
#pragma unroll 1
        for (int img = 0; img < C2_IMGS; ++img) {
            int s = 0;
#pragma unroll
            for (int dy = 0; dy < 5; ++dy)
#pragma unroll
                for (int dx = 0; dx < 5; ++dx) s += pc[img][(y + dy) * 14 + xx + dx];
            PB[img][t] = s;
        }
    }
    __syncthreads();
    int lane = t & 31, w = t >> 5;
#pragma unroll 1
    for (int k = 0; k < 4; ++k) {
        int f = k * 320 + t;
        int valid = f < 1250;
        int oc = 0, r = 0, cx = 0;
        if (valid) {
            oc = f / 25; int rem = f - oc * 25; r = rem / 5; cx = rem - r * 5;
        }
#pragma unroll 1
        for (int img = 0; img < C2_IMGS; ++img) {
            int bitP = 0, bitN = 0;
            if (valid) {
                unsigned bp[6][6];
#pragma unroll
                for (int rr = 0; rr < 6; ++rr)
#pragma unroll
                    for (int cc = 0; cc < 6; ++cc)
                        bp[rr][cc] = Bs[img][(2 * r + rr) * 14 + 2 * cx + cc];
                const unsigned* W = &Wps[oc * 25];
                int best = -1000000;
#pragma unroll
                for (int oy = 0; oy < 2; ++oy) {
#pragma unroll
                    for (int ox = 0; ox < 2; ++ox) {
                        int acc = 0;
#pragma unroll
                        for (int dy = 0; dy < 5; ++dy)
#pragma unroll
                            for (int dx = 0; dx < 5; ++dx)
                                acc += __popc(bp[oy + dy][ox + dx] & W[dy * 5 + dx]);
                        int v = 2 * acc - PB[img][(2 * r + oy) * 10 + 2 * cx + ox];
                        if (zf) {  // uniform, never taken with this dataset
                            const unsigned* Wz = &Wzs[oc * 25];
                            int az = 0;
                            for (int dy = 0; dy < 5; ++dy)
                                for (int dx = 0; dx < 5; ++dx)
                                    az += __popc(bp[oy + dy][ox + dx] & Wz[dy * 5 + dx]);
                            v += az;
                        }
                        best = max(best, v);
                    }
                }
                bitP = best > 0; bitN = best < 0;
            }
            unsigned mp = __ballot_sync(0xffffffffu, bitP);
            unsigned mn = __ballot_sync(0xffffffffu, bitN);
            if (lane == 0) {
                int wi = k * 10 + w;
                g_Bp[(size_t)(n0 + img) * 40 + wi] = mp;
                g_Bn[(size_t)(n0 + img) * 40 + wi] = mn;
            }
        }
    }
}

// ---------------- K4: binary linear (XNOR-LOP3) + clip + fc ---------------
__global__ __launch_bounds__(256) void k_dense(const float* __restrict__ fcw,
                                               const float* __restrict__ fcb,
                                               float* __restrict__ out) {
    extern __shared__ unsigned sm[];
    unsigned* Ws  = sm;                       // 500*41 (padded, conflict-free)
    unsigned* Bps = Ws + 500 * 41;            // 8*40  sign bit-plane (+1)
    unsigned* Bns = Bps + 8 * 40;             // 8*40  sign bit-plane (-1), zf path only
    unsigned* Us  = Bns + 8 * 40;             // 8*40  nonzero mask = Bp|Bn
    int*      pcU = (int*)(Us + 8 * 40);      // 8
    float*    hs  = (float*)(pcU + 8);        // 8*500
    int t = threadIdx.x;
    int n0 = blockIdx.x * 8;
    for (int i = t; i < 500 * 40; i += 256) Ws[(i / 40) * 41 + (i % 40)] = g_wpl[i];
    for (int i = t; i < 320; i += 256) {
        int img = i / 40, wi = i % 40;
        unsigned bp = g_Bp[(size_t)(n0 + img) * 40 + wi];
        unsigned bn = g_Bn[(size_t)(n0 + img) * 40 + wi];
        Bps[img * 40 + wi] = bp;
        Bns[img * 40 + wi] = bn;
        Us[img * 40 + wi]  = bp | bn;
    }
    __syncthreads();
    if (t < 8) {
        int s = 0;
        for (int k = 0; k < 40; ++k) s += __popc(Us[t * 40 + k]);
        pcU[t] = s;
    }
    __syncthreads();
    int zf = g_zflagl;
    for (int j = t; j < 500; j += 256) {
        unsigned wr[40];
#pragma unroll
        for (int k = 0; k < 40; ++k) wr[k] = Ws[j * 41 + k];
        float al = g_alphal[j];
#pragma unroll 1
        for (int img = 0; img < 8; ++img) {
            int m = 0;
#pragma unroll
            for (int k = 0; k < 40; ++k) {
                // agreement over nonzero lanes: one LOP3 per word
                m += __popc((~(Bps[img * 40 + k] ^ wr[k])) & Us[img * 40 + k]);
            }
            int vi = 2 * m - pcU[img];
            if (zf) {  // uniform, never taken with this dataset
                int cp = 0, cn = 0;
                for (int k = 0; k < 40; ++k) {
                    unsigned z = g_wzl[j * 40 + k];
                    cp += __popc(Bps[img * 40 + k] & z);
                    cn += __popc(Bns[img * 40 + k] & z);
                }
                vi += cp - cn;
            }
            float h = fminf(fmaxf((float)vi * al, -1.f), 1.f);
            hs[img * 500 + j] = h;
        }
    }
    __syncthreads();
    int w = t >> 5, lane = t & 31;   // warp w -> image w
    for (int lg = 0; lg < 10; ++lg) {
        float p = 0.f;
        for (int j = lane; j < 500; j += 32)
            p += hs[w * 500 + j] * __ldg(&fcw[lg * 500 + j]);
#pragma unroll
        for (int o = 16; o; o >>= 1) p += __shfl_down_sync(0xffffffffu, p, o);
        if (lane == 0) out[(size_t)(n0 + w) * 10 + lg] = p + fcb[lg];
    }
}

// ---------------- launch ---------------------------------------------------
extern "C" void kernel_launch(void* const* d_in, const int* in_sizes, int n_in,
                              void* d_out, int out_size) {
    const float* x   = (const float*)d_in[0];
    const float* w1  = (const float*)d_in[1];
    const float* w2  = (const float*)d_in[2];
    const float* wl  = (const float*)d_in[3];
    const float* fcw = (const float*)d_in[4];
    const float* fcb = (const float*)d_in[5];
    float* out = (float*)d_out;

    size_t dense_smem = (500 * 41 + 8 * 40 * 3 + 8) * 4 + 8 * 500 * 4;
    cudaFuncSetAttribute(k_dense, cudaFuncAttributeMaxDynamicSharedMemorySize,
                         (int)dense_smem);

    k_pre<<<207, 256>>>(x, w2, wl);
    k_thr<<<1, 1024>>>(w1);
    k_conv1<<<8192, 224>>>(x, w1);
    k_conv2<<<N_IMG / C2_IMGS, 320>>>();
    k_dense<<<1024, 256, dense_smem>>>(fcw, fcb, out);
}